// round 6
// baseline (speedup 1.0000x reference)
#include <cuda_runtime.h>
#include <cstdint>

#define N_NODES 50000
#define N_EDGES 800000
#define D 128
#define NCLS 64
#define SCAN_B 1024
#define SCAN_NBLK ((N_NODES + SCAN_B - 1) / SCAN_B)   // 49

// ---------------------------------------------------------------------------
// Device-global scratch
// ---------------------------------------------------------------------------
__device__ __align__(16) float g_y[N_NODES * D];
__device__ __align__(16) float g_h[N_NODES * D];
__device__ __align__(16) float g_z[N_NODES * D];
__device__ int g_row_ptr[N_NODES + 1];
__device__ int g_cursor[N_NODES];
__device__ int g_cnt[N_NODES];
__device__ int g_col[N_EDGES];
__device__ int g_partials[SCAN_NBLK];

// Streams + events created once at static-init (outside capture & mem checkpoints)
struct OverlapCtx {
    cudaStream_t s1;
    cudaEvent_t evFork, evCSR;
    OverlapCtx() {
        cudaStreamCreateWithFlags(&s1, cudaStreamNonBlocking);
        cudaEventCreateWithFlags(&evFork, cudaEventDisableTiming);
        cudaEventCreateWithFlags(&evCSR,  cudaEventDisableTiming);
    }
};
static OverlapCtx g_ctx;

// ---------------------------------------------------------------------------
// CSR: zero -> hist(x4 MLP) -> scan_block -> scan_add(fused partials) -> fill
// ---------------------------------------------------------------------------
__global__ void zero_cnt_kernel(int* __restrict__ cnt) {
    int i = blockIdx.x * blockDim.x + threadIdx.x;
    if (i < N_NODES) cnt[i] = 0;
}

__global__ void __launch_bounds__(256) hist_kernel(
    const int* __restrict__ dst, int* __restrict__ cnt)
{
    int base = (blockIdx.x * blockDim.x + threadIdx.x) * 4;
    if (base + 3 < N_EDGES) {
        int4 d4 = *reinterpret_cast<const int4*>(dst + base);
        atomicAdd(cnt + d4.x, 1);
        atomicAdd(cnt + d4.y, 1);
        atomicAdd(cnt + d4.z, 1);
        atomicAdd(cnt + d4.w, 1);
    } else {
        for (int e = base; e < N_EDGES; e++) atomicAdd(cnt + dst[e], 1);
    }
}

__global__ void __launch_bounds__(SCAN_B) scan_block_kernel(
    const int* __restrict__ cnt, int* __restrict__ row_ptr, int* __restrict__ partials)
{
    __shared__ int wsum[32];
    int i = blockIdx.x * SCAN_B + threadIdx.x;
    int lane = threadIdx.x & 31;
    int wid  = threadIdx.x >> 5;

    int v = (i < N_NODES) ? cnt[i] : 0;
    int x = v;
    #pragma unroll
    for (int off = 1; off < 32; off <<= 1) {
        int t = __shfl_up_sync(0xffffffffu, x, off);
        if (lane >= off) x += t;
    }
    if (lane == 31) wsum[wid] = x;
    __syncthreads();
    if (wid == 0) {
        int w = wsum[lane];
        #pragma unroll
        for (int off = 1; off < 32; off <<= 1) {
            int t = __shfl_up_sync(0xffffffffu, w, off);
            if (lane >= off) w += t;
        }
        wsum[lane] = w;
    }
    __syncthreads();

    int excl = x - v + (wid ? wsum[wid - 1] : 0);
    if (i < N_NODES) row_ptr[i] = excl;
    if (threadIdx.x == SCAN_B - 1) partials[blockIdx.x] = excl + v;
}

__global__ void __launch_bounds__(SCAN_B) scan_add_kernel(
    int* __restrict__ row_ptr, int* __restrict__ cursor, const int* __restrict__ partials)
{
    __shared__ int sp[SCAN_NBLK];
    if (threadIdx.x < SCAN_NBLK) sp[threadIdx.x] = partials[threadIdx.x];
    __syncthreads();
    if (threadIdx.x == 0) {
        int run = 0;
        #pragma unroll
        for (int k = 0; k < SCAN_NBLK; k++) { int t = sp[k]; sp[k] = run; run += t; }
    }
    __syncthreads();

    int i = blockIdx.x * SCAN_B + threadIdx.x;
    if (i < N_NODES) {
        int r = row_ptr[i] + sp[blockIdx.x];
        row_ptr[i] = r;
        cursor[i]  = r;
    }
    if (i == 0) row_ptr[N_NODES] = N_EDGES;
}

__global__ void __launch_bounds__(256) fill_kernel(
    const int* __restrict__ src, const int* __restrict__ dst,
    int* __restrict__ cursor, int* __restrict__ col)
{
    int base = (blockIdx.x * blockDim.x + threadIdx.x) * 4;
    if (base + 3 < N_EDGES) {
        int4 d4 = *reinterpret_cast<const int4*>(dst + base);
        int4 s4 = *reinterpret_cast<const int4*>(src + base);
        int p0 = atomicAdd(cursor + d4.x, 1);
        int p1 = atomicAdd(cursor + d4.y, 1);
        int p2 = atomicAdd(cursor + d4.z, 1);
        int p3 = atomicAdd(cursor + d4.w, 1);
        col[p0] = s4.x; col[p1] = s4.y; col[p2] = s4.z; col[p3] = s4.w;
    } else {
        for (int e = base; e < N_EDGES; e++) {
            int pos = atomicAdd(cursor + dst[e], 1);
            col[pos] = src[e];
        }
    }
}

// ---------------------------------------------------------------------------
// f32x2 GEMM (2 fp32 FMAs / instruction, full fp32 precision)
// y[n,j] = sum_k A[n,k] * W[j,k].  BM=64 rows, 256 threads.
// NOUT=128: TX=16,TY=16,RPT=4.  NOUT=64: TX=8,TY=32,RPT=2.
// ---------------------------------------------------------------------------
template <int NOUT>
__global__ void __launch_bounds__(256) gemm_kernel(
    const float* __restrict__ A, const float* __restrict__ W, float* __restrict__ y)
{
    constexpr int BM  = 64;
    constexpr int TX  = NOUT / 8;
    constexpr int TY  = 256 / TX;
    constexpr int RPT = BM / TY;
    constexpr int SXS = D + 4;
    constexpr int SWS = NOUT + 4;

    extern __shared__ float smem[];
    float* sX = smem;
    float* sW = smem + BM * SXS;

    const int tid  = threadIdx.x;
    const int row0 = blockIdx.x * BM;

    #pragma unroll
    for (int i = tid; i < BM * (D / 4); i += 256) {
        int r  = i >> 5;
        int c4 = i & 31;
        int gr = row0 + r;
        float4 v = make_float4(0.f, 0.f, 0.f, 0.f);
        if (gr < N_NODES) v = reinterpret_cast<const float4*>(A + (size_t)gr * D)[c4];
        reinterpret_cast<float4*>(sX + r * SXS)[c4] = v;
    }
    #pragma unroll
    for (int i = tid; i < NOUT * (D / 4); i += 256) {
        int n  = i >> 5;
        int k4 = i & 31;
        float4 v = reinterpret_cast<const float4*>(W)[i];
        sW[(k4 * 4 + 0) * SWS + n] = v.x;
        sW[(k4 * 4 + 1) * SWS + n] = v.y;
        sW[(k4 * 4 + 2) * SWS + n] = v.z;
        sW[(k4 * 4 + 3) * SWS + n] = v.w;
    }
    __syncthreads();

    const int tx = tid % TX;
    const int ty = tid / TX;
    const int cbase = tx * 8;
    const int rbase = ty * RPT;

    unsigned long long acc[RPT][4];
    #pragma unroll
    for (int r = 0; r < RPT; r++)
        #pragma unroll
        for (int c = 0; c < 4; c++) acc[r][c] = 0ULL;

    #pragma unroll 4
    for (int k = 0; k < D; k++) {
        const ulonglong2* bp = reinterpret_cast<const ulonglong2*>(sW + k * SWS + cbase);
        ulonglong2 bA = bp[0];
        ulonglong2 bB = bp[1];
        #pragma unroll
        for (int r = 0; r < RPT; r++) {
            float a = sX[(rbase + r) * SXS + k];
            unsigned long long a2;
            asm("mov.b64 %0, {%1, %1};" : "=l"(a2) : "f"(a));
            asm("fma.rn.f32x2 %0, %1, %2, %0;" : "+l"(acc[r][0]) : "l"(a2), "l"(bA.x));
            asm("fma.rn.f32x2 %0, %1, %2, %0;" : "+l"(acc[r][1]) : "l"(a2), "l"(bA.y));
            asm("fma.rn.f32x2 %0, %1, %2, %0;" : "+l"(acc[r][2]) : "l"(a2), "l"(bB.x));
            asm("fma.rn.f32x2 %0, %1, %2, %0;" : "+l"(acc[r][3]) : "l"(a2), "l"(bB.y));
        }
    }

    #pragma unroll
    for (int r = 0; r < RPT; r++) {
        int row = row0 + rbase + r;
        if (row >= N_NODES) continue;
        float o[8];
        #pragma unroll
        for (int c = 0; c < 4; c++)
            asm("mov.b64 {%0, %1}, %2;" : "=f"(o[2*c]), "=f"(o[2*c+1]) : "l"(acc[r][c]));
        float4* dst4 = reinterpret_cast<float4*>(y + (size_t)row * NOUT + cbase);
        dst4[0] = make_float4(o[0], o[1], o[2], o[3]);
        dst4[1] = make_float4(o[4], o[5], o[6], o[7]);
    }
}

// ---------------------------------------------------------------------------
// CSR aggregation + bias + relu. One warp per node, 8 gathers in flight.
// ---------------------------------------------------------------------------
__global__ void __launch_bounds__(256) aggregate128_kernel(
    const float* __restrict__ y, const int* __restrict__ row_ptr,
    const int* __restrict__ col, const float* __restrict__ bias,
    float* __restrict__ out)
{
    int node = (blockIdx.x * blockDim.x + threadIdx.x) >> 5;
    int lane = threadIdx.x & 31;
    if (node >= N_NODES) return;

    int beg = __ldg(row_ptr + node);
    int end = __ldg(row_ptr + node + 1);

    const float4* base = reinterpret_cast<const float4*>(y);
    float4 a0 = base[(size_t)node * 32 + lane];
    float4 a1 = make_float4(0.f, 0.f, 0.f, 0.f);

    int j = beg;
    for (; j + 7 < end; j += 8) {
        int c[8];
        #pragma unroll
        for (int u = 0; u < 8; u++) c[u] = __ldg(col + j + u);
        float4 v[8];
        #pragma unroll
        for (int u = 0; u < 8; u++) v[u] = base[(size_t)c[u] * 32 + lane];
        #pragma unroll
        for (int u = 0; u < 8; u += 2) {
            a0.x += v[u].x;   a0.y += v[u].y;   a0.z += v[u].z;   a0.w += v[u].w;
            a1.x += v[u+1].x; a1.y += v[u+1].y; a1.z += v[u+1].z; a1.w += v[u+1].w;
        }
    }
    for (; j < end; j++) {
        int c0 = __ldg(col + j);
        float4 v0 = base[(size_t)c0 * 32 + lane];
        a0.x += v0.x; a0.y += v0.y; a0.z += v0.z; a0.w += v0.w;
    }
    a0.x += a1.x; a0.y += a1.y; a0.z += a1.z; a0.w += a1.w;

    float4 b = reinterpret_cast<const float4*>(bias)[lane];
    float4 o;
    o.x = fmaxf(a0.x + b.x, 0.f);
    o.y = fmaxf(a0.y + b.y, 0.f);
    o.z = fmaxf(a0.z + b.z, 0.f);
    o.w = fmaxf(a0.w + b.w, 0.f);
    reinterpret_cast<float4*>(out)[(size_t)node * 32 + lane] = o;
}

__global__ void __launch_bounds__(256) aggregate64_kernel(
    const float* __restrict__ y, const int* __restrict__ row_ptr,
    const int* __restrict__ col, const float* __restrict__ bias,
    float* __restrict__ out)
{
    int node = (blockIdx.x * blockDim.x + threadIdx.x) >> 5;
    int lane = threadIdx.x & 31;
    if (node >= N_NODES) return;

    int beg = __ldg(row_ptr + node);
    int end = __ldg(row_ptr + node + 1);

    const float2* base = reinterpret_cast<const float2*>(y);
    float2 a0 = base[(size_t)node * 32 + lane];
    float2 a1 = make_float2(0.f, 0.f);

    int j = beg;
    for (; j + 7 < end; j += 8) {
        int c[8];
        #pragma unroll
        for (int u = 0; u < 8; u++) c[u] = __ldg(col + j + u);
        float2 v[8];
        #pragma unroll
        for (int u = 0; u < 8; u++) v[u] = base[(size_t)c[u] * 32 + lane];
        #pragma unroll
        for (int u = 0; u < 8; u += 2) {
            a0.x += v[u].x;   a0.y += v[u].y;
            a1.x += v[u+1].x; a1.y += v[u+1].y;
        }
    }
    for (; j < end; j++) {
        int c0 = __ldg(col + j);
        float2 v0 = base[(size_t)c0 * 32 + lane];
        a0.x += v0.x; a0.y += v0.y;
    }
    a0.x += a1.x; a0.y += a1.y;

    float2 b = reinterpret_cast<const float2*>(bias)[lane];
    float2 o;
    o.x = fmaxf(a0.x + b.x, 0.f);
    o.y = fmaxf(a0.y + b.y, 0.f);
    reinterpret_cast<float2*>(out)[(size_t)node * 32 + lane] = o;
}

// ---------------------------------------------------------------------------
// Launch: CSR (s1) runs concurrently with layer-1 GEMM (s0); everything else
// serial full-size on s0 (the R3 structure that measured fastest).
// ---------------------------------------------------------------------------
extern "C" void kernel_launch(void* const* d_in, const int* in_sizes, int n_in,
                              void* d_out, int out_size)
{
    const float* in_feat = (const float*)d_in[0];
    const float* W1 = (const float*)d_in[1];
    const float* b1 = (const float*)d_in[2];
    const float* W2 = (const float*)d_in[3];
    const float* b2 = (const float*)d_in[4];
    const float* W3 = (const float*)d_in[5];
    const float* b3 = (const float*)d_in[6];
    const int*   src = (const int*)d_in[7];
    const int*   dst = (const int*)d_in[8];
    float* out = (float*)d_out;

    float *y, *h, *z;
    int *row_ptr, *cursor, *cnt, *col, *partials;
    cudaGetSymbolAddress((void**)&y, g_y);
    cudaGetSymbolAddress((void**)&h, g_h);
    cudaGetSymbolAddress((void**)&z, g_z);
    cudaGetSymbolAddress((void**)&row_ptr, g_row_ptr);
    cudaGetSymbolAddress((void**)&cursor, g_cursor);
    cudaGetSymbolAddress((void**)&cnt, g_cnt);
    cudaGetSymbolAddress((void**)&col, g_col);
    cudaGetSymbolAddress((void**)&partials, g_partials);

    const int smem128 = (64 * (D + 4) + D * (128 + 4)) * (int)sizeof(float);
    const int smem64  = (64 * (D + 4) + D * (64 + 4))  * (int)sizeof(float);
    cudaFuncSetAttribute(gemm_kernel<128>,
                         cudaFuncAttributeMaxDynamicSharedMemorySize, smem128);
    cudaFuncSetAttribute(gemm_kernel<64>,
                         cudaFuncAttributeMaxDynamicSharedMemorySize, smem64);

    cudaStream_t s0 = 0;
    cudaStream_t s1 = g_ctx.s1;

    const int node_blocks  = (N_NODES + 255) / 256;
    const int edge4_blocks = (N_EDGES / 4 + 255) / 256;
    const int gemm_blocks  = (N_NODES + 63) / 64;
    const int agg_blocks   = (N_NODES * 32 + 255) / 256;

    // Fork: CSR on s1 concurrent with layer-1 GEMM on s0
    cudaEventRecord(g_ctx.evFork, s0);
    cudaStreamWaitEvent(s1, g_ctx.evFork, 0);

    gemm_kernel<128><<<gemm_blocks, 256, smem128, s0>>>(in_feat, W1, y);

    zero_cnt_kernel<<<node_blocks, 256, 0, s1>>>(cnt);
    hist_kernel<<<edge4_blocks, 256, 0, s1>>>(dst, cnt);
    scan_block_kernel<<<SCAN_NBLK, SCAN_B, 0, s1>>>(cnt, row_ptr, partials);
    scan_add_kernel<<<SCAN_NBLK, SCAN_B, 0, s1>>>(row_ptr, cursor, partials);
    fill_kernel<<<edge4_blocks, 256, 0, s1>>>(src, dst, cursor, col);
    cudaEventRecord(g_ctx.evCSR, s1);
    cudaStreamWaitEvent(s0, g_ctx.evCSR, 0);

    // ---- Layer 1 boundary: h = relu(y + Ay + b1) ----
    aggregate128_kernel<<<agg_blocks, 256, 0, s0>>>(y, row_ptr, col, b1, h);

    // ---- Layer 2: z = h@W2 ; y = relu(z + Az + b2) ----
    gemm_kernel<128><<<gemm_blocks, 256, smem128, s0>>>(h, W2, z);
    aggregate128_kernel<<<agg_blocks, 256, 0, s0>>>(z, row_ptr, col, b2, y);

    // ---- Layer 3: h = y@W3 (64) ; out = relu(h + Ah + b3) ----
    gemm_kernel<64><<<gemm_blocks, 256, smem64, s0>>>(y, W3, h);
    aggregate64_kernel<<<agg_blocks, 256, 0, s0>>>(h, row_ptr, col, b3, out);
}